// round 4
// baseline (speedup 1.0000x reference)
#include <cuda_runtime.h>

// Single-kernel inclusive cumsum along leading axis of xs[T, D] (fp32).
// Output: d_out[0:D] = final carry, d_out[D:] = ys[T,D].
//
// Phase A: per-chunk column sums; xs loaded with L2 evict_last cache policy
//          (via createpolicy + ld.global.L2::cache_hint) so it pins in L2.
// Grid barrier via atomic counter (grid = 256 CTAs << residency capacity).
// Prefix: each thread sums predecessor aggregates with independent loads.
// Phase B: re-read xs (L2 hits, evict-first), add prefix, stream ys out.

#define THREADS 256
#define C_F4    256            // float4 columns per group (1024 floats)
#define CHUNKS_TARGET 64
#define MAX_SP4 2048

static __device__ float4 g_agg4[CHUNKS_TARGET * 2 * MAX_SP4]; // aggregates
static __device__ int    g_counter;

__device__ __forceinline__ unsigned long long mk_policy_keep() {
    unsigned long long pol;
    asm("createpolicy.fractional.L2::evict_last.b64 %0, 1.0;" : "=l"(pol));
    return pol;
}
__device__ __forceinline__ float4 ldg_keep(const float4* p, unsigned long long pol) {
    float4 v;
    asm volatile("ld.global.L2::cache_hint.v4.f32 {%0,%1,%2,%3}, [%4], %5;"
                 : "=f"(v.x), "=f"(v.y), "=f"(v.z), "=f"(v.w)
                 : "l"(p), "l"(pol));
    return v;
}
__device__ __forceinline__ int ld_acquire(const int* p) {
    int v;
    asm volatile("ld.acquire.gpu.global.b32 %0, [%1];" : "=r"(v) : "l"(p) : "memory");
    return v;
}
__device__ __forceinline__ float4 f4add(float4 a, float4 b) {
    return make_float4(a.x + b.x, a.y + b.y, a.z + b.z, a.w + b.w);
}

__global__ __launch_bounds__(THREADS, 4)
void scan_gridsync(const float4* __restrict__ xs4, float4* __restrict__ ys4,
                   float4* __restrict__ carry4,
                   int stride4, int sp4, int T, int rows, int chunks, int ncta) {
    const int g   = blockIdx.x;
    const int c   = blockIdx.y;
    const int t4  = threadIdx.x;
    const int gc4 = g * C_F4 + t4;
    const bool act = gc4 < stride4;

    const int row0 = c * rows;
    const int nr   = min(rows, T - row0);
    const float4* xp = xs4 + (size_t)row0 * stride4 + gc4;
    const unsigned long long pol = mk_policy_keep();

    // ---- Phase A: column sum for this chunk, pin xs in L2 ----
    float4 agg = make_float4(0.f, 0.f, 0.f, 0.f);
    if (act) {
        int r = 0;
        for (; r + 8 <= nr; r += 8) {
            float4 v0 = ldg_keep(xp + (size_t)(r + 0) * stride4, pol);
            float4 v1 = ldg_keep(xp + (size_t)(r + 1) * stride4, pol);
            float4 v2 = ldg_keep(xp + (size_t)(r + 2) * stride4, pol);
            float4 v3 = ldg_keep(xp + (size_t)(r + 3) * stride4, pol);
            float4 v4 = ldg_keep(xp + (size_t)(r + 4) * stride4, pol);
            float4 v5 = ldg_keep(xp + (size_t)(r + 5) * stride4, pol);
            float4 v6 = ldg_keep(xp + (size_t)(r + 6) * stride4, pol);
            float4 v7 = ldg_keep(xp + (size_t)(r + 7) * stride4, pol);
            agg = f4add(agg, v0); agg = f4add(agg, v1);
            agg = f4add(agg, v2); agg = f4add(agg, v3);
            agg = f4add(agg, v4); agg = f4add(agg, v5);
            agg = f4add(agg, v6); agg = f4add(agg, v7);
        }
        for (; r < nr; ++r) agg = f4add(agg, ldg_keep(xp + (size_t)r * stride4, pol));
        g_agg4[(size_t)c * sp4 + gc4] = agg;
    }
    __threadfence();
    __syncthreads();
    if (threadIdx.x == 0) {
        atomicAdd(&g_counter, 1);
        while (ld_acquire(&g_counter) < ncta) __nanosleep(64);
    }
    __syncthreads();

    // ---- Exclusive prefix: independent loads over predecessors ----
    float4 ex = make_float4(0.f, 0.f, 0.f, 0.f);
    if (act) {
        int p = 0;
        for (; p + 4 <= c; p += 4) {
            float4 a0 = g_agg4[(size_t)(p + 0) * sp4 + gc4];
            float4 a1 = g_agg4[(size_t)(p + 1) * sp4 + gc4];
            float4 a2 = g_agg4[(size_t)(p + 2) * sp4 + gc4];
            float4 a3 = g_agg4[(size_t)(p + 3) * sp4 + gc4];
            ex = f4add(ex, f4add(f4add(a0, a1), f4add(a2, a3)));
        }
        for (; p < c; ++p) ex = f4add(ex, g_agg4[(size_t)p * sp4 + gc4]);
        if (c == chunks - 1) carry4[gc4] = f4add(ex, agg);
    }

    // ---- Phase B: re-read (L2 hits), accumulate, stream out ----
    if (act) {
        float4* yp = ys4 + (size_t)row0 * stride4 + gc4;
        float4 acc = ex;
        for (int r = 0; r < nr; ++r) {
            float4 v = __ldcs(xp + (size_t)r * stride4);
            acc = f4add(acc, v);
            __stcs(yp + (size_t)r * stride4, acc);
        }
    }
}

// ---------------------------------------------------------------------------
extern "C" void kernel_launch(void* const* d_in, const int* in_sizes, int n_in,
                              void* d_out, int out_size) {
    const float* xs = (const float*)d_in[0];
    float* out = (float*)d_out;

    const int total = in_sizes[0];          // T * D
    int D = out_size - total;
    if (D <= 0 || total % D != 0) D = 4096;
    const int T = total / D;

    const int stride4 = D / 4;
    const int ngroups = (stride4 + C_F4 - 1) / C_F4;
    const int sp4     = ngroups * C_F4;

    // chunks*ngroups must stay well under residency capacity for the barrier.
    int chunks = CHUNKS_TARGET;
    while ((long long)chunks * ngroups > 512 && chunks > 1) chunks >>= 1;
    if (chunks > T) chunks = T;
    const int rows = (T + chunks - 1) / chunks;
    chunks = (T + rows - 1) / rows;
    const int ncta = ngroups * chunks;

    float* carry = out;
    float* ys    = out + D;

    void* cnt = nullptr;
    cudaGetSymbolAddress(&cnt, g_counter);
    cudaMemsetAsync(cnt, 0, sizeof(int));

    dim3 grid(ngroups, chunks);
    scan_gridsync<<<grid, THREADS>>>((const float4*)xs, (float4*)ys,
                                     (float4*)carry, stride4, sp4, T,
                                     rows, chunks, ncta);
}

// round 5
// speedup vs baseline: 1.2838x; 1.2838x over previous
#include <cuda_runtime.h>

// Inclusive cumsum along leading axis of xs[T, D] (fp32, row-major).
// Output: d_out[0:D] = final carry, d_out[D:] = ys[T,D].
//
// 3-pass, exploiting cross-launch L2 persistence:
//  pass1: per-chunk column sums, xs pinned in L2 via evict_last policy
//  pass2: exclusive scan of chunk sums (L2-resident), writes carry
//  pass3: re-read xs (mostly L2 hits), add prefix, stream ys (evict-first)

#define SCAN_THREADS 256
#define MAX_CHUNKS   256
#define MAX_D        8192

static __device__ float g_partials[MAX_CHUNKS * MAX_D];

__device__ __forceinline__ unsigned long long mk_policy_keep() {
    unsigned long long pol;
    asm("createpolicy.fractional.L2::evict_last.b64 %0, 1.0;" : "=l"(pol));
    return pol;
}
__device__ __forceinline__ float4 ldg_keep(const float4* p, unsigned long long pol) {
    float4 v;
    asm volatile("ld.global.L2::cache_hint.v4.f32 {%0,%1,%2,%3}, [%4], %5;"
                 : "=f"(v.x), "=f"(v.y), "=f"(v.z), "=f"(v.w)
                 : "l"(p), "l"(pol));
    return v;
}
__device__ __forceinline__ float4 f4add(float4 a, float4 b) {
    return make_float4(a.x + b.x, a.y + b.y, a.z + b.z, a.w + b.w);
}

// ---------------------------------------------------------------------------
// Pass 1: grid = (stride4/256, chunks). One float4-column x R rows per thread.
__global__ __launch_bounds__(SCAN_THREADS)
void scan_pass1(const float4* __restrict__ xs4, int stride4, int R) {
    const int col4 = blockIdx.x * blockDim.x + threadIdx.x;
    const int chunk = blockIdx.y;
    if (col4 >= stride4) return;

    const float4* xp = xs4 + (size_t)chunk * R * stride4 + col4;
    const unsigned long long pol = mk_policy_keep();

    float4 acc = make_float4(0.f, 0.f, 0.f, 0.f);
#pragma unroll 8
    for (int i = 0; i < R; ++i)
        acc = f4add(acc, ldg_keep(xp + (size_t)i * stride4, pol));

    reinterpret_cast<float4*>(g_partials)[(size_t)chunk * stride4 + col4] = acc;
}

// ---------------------------------------------------------------------------
// Pass 2: exclusive scan over chunks per column; final value -> carry.
__global__ __launch_bounds__(SCAN_THREADS)
void scan_pass2(float* __restrict__ carry_out, int D, int chunks) {
    const int col = blockIdx.x * blockDim.x + threadIdx.x;
    if (col >= D) return;

    float running = 0.f;
    int c = 0;
    for (; c + 8 <= chunks; c += 8) {
        float s0 = g_partials[(size_t)(c + 0) * D + col];
        float s1 = g_partials[(size_t)(c + 1) * D + col];
        float s2 = g_partials[(size_t)(c + 2) * D + col];
        float s3 = g_partials[(size_t)(c + 3) * D + col];
        float s4 = g_partials[(size_t)(c + 4) * D + col];
        float s5 = g_partials[(size_t)(c + 5) * D + col];
        float s6 = g_partials[(size_t)(c + 6) * D + col];
        float s7 = g_partials[(size_t)(c + 7) * D + col];
        g_partials[(size_t)(c + 0) * D + col] = running; running += s0;
        g_partials[(size_t)(c + 1) * D + col] = running; running += s1;
        g_partials[(size_t)(c + 2) * D + col] = running; running += s2;
        g_partials[(size_t)(c + 3) * D + col] = running; running += s3;
        g_partials[(size_t)(c + 4) * D + col] = running; running += s4;
        g_partials[(size_t)(c + 5) * D + col] = running; running += s5;
        g_partials[(size_t)(c + 6) * D + col] = running; running += s6;
        g_partials[(size_t)(c + 7) * D + col] = running; running += s7;
    }
    for (; c < chunks; ++c) {
        float s = g_partials[(size_t)c * D + col];
        g_partials[(size_t)c * D + col] = running;
        running += s;
    }
    carry_out[col] = running;
}

// ---------------------------------------------------------------------------
// Pass 3: seed with exclusive prefix, re-read xs (L2 hits), write ys.
__global__ __launch_bounds__(SCAN_THREADS)
void scan_pass3(const float4* __restrict__ xs4, float4* __restrict__ ys4,
                int stride4, int R) {
    const int col4 = blockIdx.x * blockDim.x + threadIdx.x;
    const int chunk = blockIdx.y;
    if (col4 >= stride4) return;

    const float4* xp = xs4 + (size_t)chunk * R * stride4 + col4;
    float4* yp = ys4 + (size_t)chunk * R * stride4 + col4;

    float4 acc =
        reinterpret_cast<const float4*>(g_partials)[(size_t)chunk * stride4 + col4];

#pragma unroll 8
    for (int i = 0; i < R; ++i) {
        float4 v = __ldcs(xp + (size_t)i * stride4);   // evict-first re-read
        acc = f4add(acc, v);
        __stcs(yp + (size_t)i * stride4, acc);          // streaming store
    }
}

// ---------------------------------------------------------------------------
extern "C" void kernel_launch(void* const* d_in, const int* in_sizes, int n_in,
                              void* d_out, int out_size) {
    const float* xs = (const float*)d_in[0];
    float* out = (float*)d_out;

    const int total = in_sizes[0];          // T * D
    int D = out_size - total;
    if (D <= 0 || total % D != 0) D = 4096;
    const int T = total / D;

    int chunks = MAX_CHUNKS;
    while (chunks > 1 && (T % chunks) != 0) chunks >>= 1;
    const int R = T / chunks;

    float* carry = out;        // [D]
    float* ys    = out + D;    // [T, D]

    const int stride4 = D / 4;
    dim3 grid1((stride4 + SCAN_THREADS - 1) / SCAN_THREADS, chunks);

    scan_pass1<<<grid1, SCAN_THREADS>>>((const float4*)xs, stride4, R);
    scan_pass2<<<(D + SCAN_THREADS - 1) / SCAN_THREADS, SCAN_THREADS>>>(carry, D, chunks);
    scan_pass3<<<grid1, SCAN_THREADS>>>((const float4*)xs, (float4*)ys, stride4, R);
}